// round 3
// baseline (speedup 1.0000x reference)
#include <cuda_runtime.h>

// Problem dims (fixed by the reference setup_inputs)
#define B_    256
#define F_    300
#define JC_   1600
#define NC_   60
#define J4_   (JC_ / 4)    // 400 float4 per frame
#define CHUNK 30           // frames per pooling block
#define NCH   (F_ / CHUNK) // 10 chunks
#define ROWS_PER_FC 4      // batch rows per FC block
#define FC_BLOCKS (B_ / ROWS_PER_FC) // 64

// Scratch (device globals: allocation-free)
__device__ float4 g_part[(size_t)B_ * NCH * J4_]; // chunk partial sums
__device__ float  g_Wt[(size_t)NC_ * JC_];        // W transposed [NC][JC]

// ---------------------------------------------------------------------------
// Kernel 0: transpose W [JC, NC] -> Wt [NC, JC], smem-tiled, 50 blocks.
// ---------------------------------------------------------------------------
__global__ __launch_bounds__(256) void transpose_kernel(
    const float* __restrict__ W) // [JC, NC]
{
    __shared__ float tile[32][NC_ + 1]; // pad -> conflict-free column reads
    const int j0 = blockIdx.x * 32;

    // load: 32 j-rows x 60 n, contiguous over W
    for (int idx = threadIdx.x; idx < 32 * NC_; idx += 256) {
        const int r = idx / NC_, c = idx - r * NC_;
        tile[r][c] = W[(size_t)(j0 + r) * NC_ + c];
    }
    __syncthreads();

    // store: for each n, 32 consecutive j (coalesced 128B)
    for (int idx = threadIdx.x; idx < 32 * NC_; idx += 256) {
        const int n = idx / 32, r = idx - n * 32;
        g_Wt[(size_t)n * JC_ + j0 + r] = tile[r][n];
    }
}

// ---------------------------------------------------------------------------
// Kernel 1: partial frame sums. grid = (B, NCH), block = 400.
// Skips the write entirely for chunks beyond len (FC won't read them).
// ---------------------------------------------------------------------------
__global__ __launch_bounds__(J4_) void pool_part_kernel(
    const float* __restrict__ x,       // [B, F, JC]
    const int*   __restrict__ lengths) // [B]
{
    const int b  = blockIdx.x;
    const int c  = blockIdx.y;
    const int j4 = threadIdx.x;

    const int len = lengths[b];
    const int f0  = c * CHUNK;
    if (f0 >= len) return;             // nothing valid in this chunk
    const int f1  = min(f0 + CHUNK, len);

    const float4* __restrict__ xb =
        reinterpret_cast<const float4*>(x + (size_t)b * F_ * JC_);

    float ax = 0.f, ay = 0.f, az = 0.f, aw = 0.f;
    int f = f0;
    for (; f + 4 <= f1; f += 4) {
        float4 v0 = xb[(size_t)(f + 0) * J4_ + j4];
        float4 v1 = xb[(size_t)(f + 1) * J4_ + j4];
        float4 v2 = xb[(size_t)(f + 2) * J4_ + j4];
        float4 v3 = xb[(size_t)(f + 3) * J4_ + j4];
        ax += v0.x + v1.x + v2.x + v3.x;
        ay += v0.y + v1.y + v2.y + v3.y;
        az += v0.z + v1.z + v2.z + v3.z;
        aw += v0.w + v1.w + v2.w + v3.w;
    }
    for (; f < f1; f++) {
        float4 v = xb[(size_t)f * J4_ + j4];
        ax += v.x; ay += v.y; az += v.z; aw += v.w;
    }
    g_part[((size_t)b * NCH + c) * J4_ + j4] = make_float4(ax, ay, az, aw);
}

// ---------------------------------------------------------------------------
// Kernel 2: fused reduce + mean + edge case + FC.
// grid = 64 blocks x 4 batch rows, block = 512 (16 warps).
// Phase A: build 4 pooled rows in shared (partials from L2; len<=1 -> frame 0).
// Phase B: warp w owns outputs n = w, w+16, w+32, w+48; loads Wt float4 once
//          per chunk and reuses across the 4 rows. Warp-shuffle reduce.
// ---------------------------------------------------------------------------
__global__ __launch_bounds__(512) void fc_kernel(
    const float* __restrict__ x,       // [B, F, JC] (len<=1 edge case)
    const int*   __restrict__ lengths, // [B]
    const float* __restrict__ bias,    // [NC]
    float*       __restrict__ out)     // [B, NC]
{
    __shared__ float4 sp[ROWS_PER_FC][J4_]; // 25.6 KB pooled rows

    const int b0 = blockIdx.x * ROWS_PER_FC;
    const int t  = threadIdx.x;

    // ---- Phase A: pooled rows into shared ----
    for (int rc = t; rc < ROWS_PER_FC * J4_; rc += 512) {
        const int r  = rc / J4_;
        const int j4 = rc - r * J4_;
        const int b  = b0 + r;
        const int len = lengths[b];
        float4 s;
        if (len <= 1) {
            s = reinterpret_cast<const float4*>(x + (size_t)b * F_ * JC_)[j4];
        } else {
            const int nch = (len + CHUNK - 1) / CHUNK;
            float ax = 0.f, ay = 0.f, az = 0.f, aw = 0.f;
            for (int c = 0; c < nch; c++) {
                float4 v = g_part[((size_t)b * NCH + c) * J4_ + j4];
                ax += v.x; ay += v.y; az += v.z; aw += v.w;
            }
            const float inv = 1.0f / (float)len;
            s = make_float4(ax * inv, ay * inv, az * inv, aw * inv);
        }
        sp[r][j4] = s;
    }
    __syncthreads();

    // ---- Phase B: 16 warps x up-to-4 outputs each ----
    const int w = t >> 5;
    const int l = t & 31;
    const int nvalid3 = (w + 48 < NC_) ? 4 : 3; // w<12 -> 4 outputs

    float acc[ROWS_PER_FC][4];
#pragma unroll
    for (int r = 0; r < ROWS_PER_FC; r++)
#pragma unroll
        for (int s = 0; s < 4; s++) acc[r][s] = 0.f;

    const float4* __restrict__ Wt4 = reinterpret_cast<const float4*>(g_Wt);

#pragma unroll 2
    for (int k = 0; k < 13; k++) {
        const int j4 = k * 32 + l;
        if (j4 < J4_) {
            float4 s0 = sp[0][j4];
            float4 s1 = sp[1][j4];
            float4 s2 = sp[2][j4];
            float4 s3 = sp[3][j4];
#pragma unroll
            for (int s = 0; s < 4; s++) {
                const int n = w + 16 * s;
                if (s < 3 || nvalid3 == 4) {
                    float4 wv = Wt4[(size_t)n * J4_ + j4];
                    acc[0][s] += s0.x * wv.x + s0.y * wv.y + s0.z * wv.z + s0.w * wv.w;
                    acc[1][s] += s1.x * wv.x + s1.y * wv.y + s1.z * wv.z + s1.w * wv.w;
                    acc[2][s] += s2.x * wv.x + s2.y * wv.y + s2.z * wv.z + s2.w * wv.w;
                    acc[3][s] += s3.x * wv.x + s3.y * wv.y + s3.z * wv.z + s3.w * wv.w;
                }
            }
        }
    }

    // warp reduce + write
#pragma unroll
    for (int r = 0; r < ROWS_PER_FC; r++) {
#pragma unroll
        for (int s = 0; s < 4; s++) {
            if (s == 3 && nvalid3 != 4) continue;
            float v = acc[r][s];
            v += __shfl_xor_sync(0xFFFFFFFF, v, 16);
            v += __shfl_xor_sync(0xFFFFFFFF, v, 8);
            v += __shfl_xor_sync(0xFFFFFFFF, v, 4);
            v += __shfl_xor_sync(0xFFFFFFFF, v, 2);
            v += __shfl_xor_sync(0xFFFFFFFF, v, 1);
            if (l == 0) {
                const int n = w + 16 * s;
                out[(size_t)(b0 + r) * NC_ + n] = v + bias[n];
            }
        }
    }
}

extern "C" void kernel_launch(void* const* d_in, const int* in_sizes, int n_in,
                              void* d_out, int out_size)
{
    const float* x       = (const float*)d_in[0];
    const int*   lengths = (const int*)  d_in[1];
    const float* W       = (const float*)d_in[2];
    const float* bias    = (const float*)d_in[3];
    float*       out     = (float*)d_out;

    transpose_kernel<<<JC_ / 32, 256>>>(W);
    dim3 grid_pool(B_, NCH);
    pool_part_kernel<<<grid_pool, J4_>>>(x, lengths);
    fc_kernel<<<FC_BLOCKS, 512>>>(x, lengths, bias, out);
}

// round 4
// speedup vs baseline: 1.1241x; 1.1241x over previous
#include <cuda_runtime.h>

// Problem dims (fixed by the reference setup_inputs)
#define B_    256
#define F_    300
#define JC_   1600
#define NC_   60
#define J4_   (JC_ / 4)    // 400 float4 per frame
#define CHUNK 30           // frames per pooling block
#define NCH   (F_ / CHUNK) // 10 chunks
#define ROWS_PER_FC 4      // batch rows per FC block
#define FC_BLOCKS (B_ / ROWS_PER_FC) // 64

// Chunk partial sums [B, NCH, J4] (device scratch: allocation-free)
__device__ float4 g_part[(size_t)B_ * NCH * J4_];

// ---------------------------------------------------------------------------
// Kernel 1: partial frame sums. grid = (B, NCH), block = 400.
// Bounded work per block (<= 30 frames); skips chunks beyond len.
// ---------------------------------------------------------------------------
__global__ __launch_bounds__(J4_) void pool_part_kernel(
    const float* __restrict__ x,       // [B, F, JC]
    const int*   __restrict__ lengths) // [B]
{
    const int b  = blockIdx.x;
    const int c  = blockIdx.y;
    const int j4 = threadIdx.x;

    const int len = lengths[b];
    const int f0  = c * CHUNK;
    if (f0 >= len) return;             // nothing valid in this chunk
    const int f1  = min(f0 + CHUNK, len);

    const float4* __restrict__ xb =
        reinterpret_cast<const float4*>(x + (size_t)b * F_ * JC_);

    float ax = 0.f, ay = 0.f, az = 0.f, aw = 0.f;
    int f = f0;
    for (; f + 4 <= f1; f += 4) {
        float4 v0 = xb[(size_t)(f + 0) * J4_ + j4];
        float4 v1 = xb[(size_t)(f + 1) * J4_ + j4];
        float4 v2 = xb[(size_t)(f + 2) * J4_ + j4];
        float4 v3 = xb[(size_t)(f + 3) * J4_ + j4];
        ax += v0.x + v1.x + v2.x + v3.x;
        ay += v0.y + v1.y + v2.y + v3.y;
        az += v0.z + v1.z + v2.z + v3.z;
        aw += v0.w + v1.w + v2.w + v3.w;
    }
    for (; f < f1; f++) {
        float4 v = xb[(size_t)f * J4_ + j4];
        ax += v.x; ay += v.y; az += v.z; aw += v.w;
    }
    g_part[((size_t)b * NCH + c) * J4_ + j4] = make_float4(ax, ay, az, aw);
}

// ---------------------------------------------------------------------------
// Kernel 2: fused reduce + mean + edge case + FC. NO transpose needed.
// grid = 64 blocks x 4 batch rows, block = 480 (15 warps).
// Phase A: build 4 pooled rows in shared (partials from L2; len<=1 -> frame 0).
// Phase B: warp w owns output quad n=4w..4w+3 (one aligned float4 of a W row).
//          Lane l walks j = l, l+32, ... : 1 LDG.128 of W + 4 smem scalars ->
//          16 independent FMA chains per thread. Warp-shuffle reduce.
// ---------------------------------------------------------------------------
__global__ __launch_bounds__(480) void fc_kernel(
    const float* __restrict__ x,       // [B, F, JC] (len<=1 edge case)
    const int*   __restrict__ lengths, // [B]
    const float* __restrict__ W,       // [JC, NC] row-major
    const float* __restrict__ bias,    // [NC]
    float*       __restrict__ out)     // [B, NC]
{
    __shared__ float sp[ROWS_PER_FC][JC_]; // 25.6 KB pooled rows

    const int b0 = blockIdx.x * ROWS_PER_FC;
    const int t  = threadIdx.x;

    // ---- Phase A: pooled rows into shared ----
    for (int rc = t; rc < ROWS_PER_FC * J4_; rc += 480) {
        const int r  = rc / J4_;
        const int j4 = rc - r * J4_;
        const int b  = b0 + r;
        const int len = lengths[b];
        float4 s;
        if (len <= 1) {
            s = reinterpret_cast<const float4*>(x + (size_t)b * F_ * JC_)[j4];
        } else {
            const int nch = (len + CHUNK - 1) / CHUNK;
            float ax = 0.f, ay = 0.f, az = 0.f, aw = 0.f;
            for (int c = 0; c < nch; c++) {
                float4 v = g_part[((size_t)b * NCH + c) * J4_ + j4];
                ax += v.x; ay += v.y; az += v.z; aw += v.w;
            }
            const float inv = 1.0f / (float)len;
            s = make_float4(ax * inv, ay * inv, az * inv, aw * inv);
        }
        reinterpret_cast<float4*>(sp[r])[j4] = s;
    }
    __syncthreads();

    // ---- Phase B: 15 warps x 4 outputs each (n = 4w .. 4w+3) ----
    const int w = t >> 5;   // 0..14
    const int l = t & 31;

    const float4* __restrict__ W4 = reinterpret_cast<const float4*>(W); // [JC][15]

    float4 a0 = make_float4(0.f, 0.f, 0.f, 0.f);
    float4 a1 = a0, a2 = a0, a3 = a0;

#pragma unroll 5
    for (int k = 0; k < JC_ / 32; k++) {       // 50 iterations
        const int j = k * 32 + l;
        const float4 wv = W4[(size_t)j * (NC_ / 4) + w];
        const float s0 = sp[0][j];
        const float s1 = sp[1][j];
        const float s2 = sp[2][j];
        const float s3 = sp[3][j];
        a0.x += s0 * wv.x; a0.y += s0 * wv.y; a0.z += s0 * wv.z; a0.w += s0 * wv.w;
        a1.x += s1 * wv.x; a1.y += s1 * wv.y; a1.z += s1 * wv.z; a1.w += s1 * wv.w;
        a2.x += s2 * wv.x; a2.y += s2 * wv.y; a2.z += s2 * wv.z; a2.w += s2 * wv.w;
        a3.x += s3 * wv.x; a3.y += s3 * wv.y; a3.z += s3 * wv.z; a3.w += s3 * wv.w;
    }

    // warp-shuffle reduce each component, then lane 0 writes the quad
    float4 accs[ROWS_PER_FC] = {a0, a1, a2, a3};
#pragma unroll
    for (int r = 0; r < ROWS_PER_FC; r++) {
        float vx = accs[r].x, vy = accs[r].y, vz = accs[r].z, vw = accs[r].w;
#pragma unroll
        for (int off = 16; off > 0; off >>= 1) {
            vx += __shfl_xor_sync(0xFFFFFFFF, vx, off);
            vy += __shfl_xor_sync(0xFFFFFFFF, vy, off);
            vz += __shfl_xor_sync(0xFFFFFFFF, vz, off);
            vw += __shfl_xor_sync(0xFFFFFFFF, vw, off);
        }
        if (l == 0) {
            const int n = 4 * w;
            float* o = out + (size_t)(b0 + r) * NC_ + n;
            o[0] = vx + bias[n + 0];
            o[1] = vy + bias[n + 1];
            o[2] = vz + bias[n + 2];
            o[3] = vw + bias[n + 3];
        }
    }
}

extern "C" void kernel_launch(void* const* d_in, const int* in_sizes, int n_in,
                              void* d_out, int out_size)
{
    const float* x       = (const float*)d_in[0];
    const int*   lengths = (const int*)  d_in[1];
    const float* W       = (const float*)d_in[2];
    const float* bias    = (const float*)d_in[3];
    float*       out     = (float*)d_out;

    dim3 grid_pool(B_, NCH);
    pool_part_kernel<<<grid_pool, J4_>>>(x, lengths);
    fc_kernel<<<FC_BLOCKS, 480>>>(x, lengths, W, bias, out);
}

// round 5
// speedup vs baseline: 1.3653x; 1.2146x over previous
#include <cuda_runtime.h>

// Problem dims (fixed by the reference setup_inputs)
#define B_    256
#define F_    300
#define JC_   1600
#define NC_   60
#define J4_   (JC_ / 4)    // 400 float4 per frame
#define CHUNK 30           // frames per pooling block
#define NCH   (F_ / CHUNK) // 10 chunks
#define ROWS_PER_FC 2      // batch rows per FC block
#define FC_BLOCKS (B_ / ROWS_PER_FC) // 128

// Chunk partial sums [B, NCH, J4] (device scratch: allocation-free)
__device__ float4 g_part[(size_t)B_ * NCH * J4_];

// ---------------------------------------------------------------------------
// Kernel 1: partial frame sums. grid = (B, NCH), block = 400.
// x loaded with __ldcs (evict-first): read-once stream must NOT evict the
// partials we are about to re-read in fc_kernel.
// ---------------------------------------------------------------------------
__global__ __launch_bounds__(J4_) void pool_part_kernel(
    const float* __restrict__ x,       // [B, F, JC]
    const int*   __restrict__ lengths) // [B]
{
    const int b  = blockIdx.x;
    const int c  = blockIdx.y;
    const int j4 = threadIdx.x;

    const int len = lengths[b];
    const int f0  = c * CHUNK;
    if (f0 >= len) return;             // nothing valid in this chunk
    const int f1  = min(f0 + CHUNK, len);

    const float4* __restrict__ xb =
        reinterpret_cast<const float4*>(x + (size_t)b * F_ * JC_);

    float ax = 0.f, ay = 0.f, az = 0.f, aw = 0.f;
    int f = f0;
    for (; f + 4 <= f1; f += 4) {
        float4 v0 = __ldcs(&xb[(size_t)(f + 0) * J4_ + j4]);
        float4 v1 = __ldcs(&xb[(size_t)(f + 1) * J4_ + j4]);
        float4 v2 = __ldcs(&xb[(size_t)(f + 2) * J4_ + j4]);
        float4 v3 = __ldcs(&xb[(size_t)(f + 3) * J4_ + j4]);
        ax += v0.x + v1.x + v2.x + v3.x;
        ay += v0.y + v1.y + v2.y + v3.y;
        az += v0.z + v1.z + v2.z + v3.z;
        aw += v0.w + v1.w + v2.w + v3.w;
    }
    for (; f < f1; f++) {
        float4 v = __ldcs(&xb[(size_t)f * J4_ + j4]);
        ax += v.x; ay += v.y; az += v.z; aw += v.w;
    }
    g_part[((size_t)b * NCH + c) * J4_ + j4] = make_float4(ax, ay, az, aw);
}

// ---------------------------------------------------------------------------
// Kernel 2: fused reduce + mean + edge case + FC.
// grid = 128 blocks x 2 batch rows, block = 512 (16 warps).
// Phase A: build 2 pooled rows in shared (partials, now L2-resident).
// Phase B: warps 0..14 each own output quad n=4w..4w+3 (aligned float4 of a
//          W row); lane l walks j = l, l+32, ...: 1 LDG.128 + 2 smem scalars
//          -> 8 independent FMA chains/thread. Warp-shuffle reduce.
// ---------------------------------------------------------------------------
__global__ __launch_bounds__(512) void fc_kernel(
    const float* __restrict__ x,       // [B, F, JC] (len<=1 edge case)
    const int*   __restrict__ lengths, // [B]
    const float* __restrict__ W,       // [JC, NC] row-major
    const float* __restrict__ bias,    // [NC]
    float*       __restrict__ out)     // [B, NC]
{
    __shared__ float sp[ROWS_PER_FC][JC_]; // 12.8 KB pooled rows

    const int b0 = blockIdx.x * ROWS_PER_FC;
    const int t  = threadIdx.x;

    // ---- Phase A: pooled rows into shared ----
    for (int rc = t; rc < ROWS_PER_FC * J4_; rc += 512) {
        const int r  = rc / J4_;
        const int j4 = rc - r * J4_;
        const int b  = b0 + r;
        const int len = lengths[b];
        float4 s;
        if (len <= 1) {
            s = reinterpret_cast<const float4*>(x + (size_t)b * F_ * JC_)[j4];
        } else {
            const int nch = (len + CHUNK - 1) / CHUNK;
            float ax = 0.f, ay = 0.f, az = 0.f, aw = 0.f;
            for (int c = 0; c < nch; c++) {
                float4 v = g_part[((size_t)b * NCH + c) * J4_ + j4];
                ax += v.x; ay += v.y; az += v.z; aw += v.w;
            }
            const float inv = 1.0f / (float)len;
            s = make_float4(ax * inv, ay * inv, az * inv, aw * inv);
        }
        reinterpret_cast<float4*>(sp[r])[j4] = s;
    }
    __syncthreads();

    // ---- Phase B: warps 0..14 x 1 output quad each (n = 4w .. 4w+3) ----
    const int w = t >> 5;   // 0..15 (warp 15 idle in phase B)
    const int l = t & 31;
    if (w >= NC_ / 4) return;

    const float4* __restrict__ W4 = reinterpret_cast<const float4*>(W); // [JC][15]

    float4 a0 = make_float4(0.f, 0.f, 0.f, 0.f);
    float4 a1 = a0;

#pragma unroll 5
    for (int k = 0; k < JC_ / 32; k++) {       // 50 iterations
        const int j = k * 32 + l;
        const float4 wv = W4[(size_t)j * (NC_ / 4) + w];
        const float s0 = sp[0][j];
        const float s1 = sp[1][j];
        a0.x += s0 * wv.x; a0.y += s0 * wv.y; a0.z += s0 * wv.z; a0.w += s0 * wv.w;
        a1.x += s1 * wv.x; a1.y += s1 * wv.y; a1.z += s1 * wv.z; a1.w += s1 * wv.w;
    }

    // warp-shuffle reduce each component, then lane 0 writes the quad
    float4 accs[ROWS_PER_FC] = {a0, a1};
#pragma unroll
    for (int r = 0; r < ROWS_PER_FC; r++) {
        float vx = accs[r].x, vy = accs[r].y, vz = accs[r].z, vw = accs[r].w;
#pragma unroll
        for (int off = 16; off > 0; off >>= 1) {
            vx += __shfl_xor_sync(0xFFFFFFFF, vx, off);
            vy += __shfl_xor_sync(0xFFFFFFFF, vy, off);
            vz += __shfl_xor_sync(0xFFFFFFFF, vz, off);
            vw += __shfl_xor_sync(0xFFFFFFFF, vw, off);
        }
        if (l == 0) {
            const int n = 4 * w;
            float* o = out + (size_t)(b0 + r) * NC_ + n;
            o[0] = vx + bias[n + 0];
            o[1] = vy + bias[n + 1];
            o[2] = vz + bias[n + 2];
            o[3] = vw + bias[n + 3];
        }
    }
}

extern "C" void kernel_launch(void* const* d_in, const int* in_sizes, int n_in,
                              void* d_out, int out_size)
{
    const float* x       = (const float*)d_in[0];
    const int*   lengths = (const int*)  d_in[1];
    const float* W       = (const float*)d_in[2];
    const float* bias    = (const float*)d_in[3];
    float*       out     = (float*)d_out;

    dim3 grid_pool(B_, NCH);
    pool_part_kernel<<<grid_pool, J4_>>>(x, lengths);
    fc_kernel<<<FC_BLOCKS, 512>>>(x, lengths, W, bias, out);
}

// round 6
// speedup vs baseline: 1.3723x; 1.0052x over previous
#include <cuda_runtime.h>

// Problem dims (fixed by the reference setup_inputs)
#define B_    256
#define F_    300
#define JC_   1600
#define NC_   60
#define J4_   (JC_ / 4)    // 400 float4 per frame
#define CHUNK 30           // frames per pooling block
#define NCH   (F_ / CHUNK) // 10 chunks
#define ROWS_PER_FC 2      // batch rows per FC block
#define FC_BLOCKS (B_ / ROWS_PER_FC) // 128
#define NGRP  8            // j-groups in fc phase B
#define JSEG  (JC_ / NGRP) // 200 j per group

// Chunk partial sums [B, NCH, J4] (device scratch: allocation-free)
__device__ float4 g_part[(size_t)B_ * NCH * J4_];

// ---------------------------------------------------------------------------
// Kernel 1: partial frame sums. grid = (B, NCH), block = 400.
// x loaded with __ldcs (evict-first stream).  ~36 us, at the HBM floor.
// ---------------------------------------------------------------------------
__global__ __launch_bounds__(J4_) void pool_part_kernel(
    const float* __restrict__ x,       // [B, F, JC]
    const int*   __restrict__ lengths) // [B]
{
    const int b  = blockIdx.x;
    const int c  = blockIdx.y;
    const int j4 = threadIdx.x;

    const int len = lengths[b];
    const int f0  = c * CHUNK;
    if (f0 >= len) return;
    const int f1  = min(f0 + CHUNK, len);

    const float4* __restrict__ xb =
        reinterpret_cast<const float4*>(x + (size_t)b * F_ * JC_);

    float ax = 0.f, ay = 0.f, az = 0.f, aw = 0.f;
    int f = f0;
    for (; f + 4 <= f1; f += 4) {
        float4 v0 = __ldcs(&xb[(size_t)(f + 0) * J4_ + j4]);
        float4 v1 = __ldcs(&xb[(size_t)(f + 1) * J4_ + j4]);
        float4 v2 = __ldcs(&xb[(size_t)(f + 2) * J4_ + j4]);
        float4 v3 = __ldcs(&xb[(size_t)(f + 3) * J4_ + j4]);
        ax += v0.x + v1.x + v2.x + v3.x;
        ay += v0.y + v1.y + v2.y + v3.y;
        az += v0.z + v1.z + v2.z + v3.z;
        aw += v0.w + v1.w + v2.w + v3.w;
    }
    for (; f < f1; f++) {
        float4 v = __ldcs(&xb[(size_t)f * J4_ + j4]);
        ax += v.x; ay += v.y; az += v.z; aw += v.w;
    }
    g_part[((size_t)b * NCH + c) * J4_ + j4] = make_float4(ax, ay, az, aw);
}

// ---------------------------------------------------------------------------
// Kernel 2: fused reduce + mean + edge case + FC.
// grid = 128 blocks x 2 batch rows, block = 512.
// Phase A: build 2 pooled rows in shared from chunk partials.
// Phase B: thread t -> n = t&63 (60 active), group g = t>>6 owns 200 j.
//          For fixed j, a group's lanes read 60 CONSECUTIVE floats of W
//          (coalesced, ~3 lines) -- kills the R5 wavefront explosion.
//          j unrolled x8 for MLP. 8x60 partials reduced in smem.
// ---------------------------------------------------------------------------
__global__ __launch_bounds__(512) void fc_kernel(
    const float* __restrict__ x,       // [B, F, JC] (len<=1 edge case)
    const int*   __restrict__ lengths, // [B]
    const float* __restrict__ W,       // [JC, NC] row-major
    const float* __restrict__ bias,    // [NC]
    float*       __restrict__ out)     // [B, NC]
{
    __shared__ float sp[ROWS_PER_FC][JC_];          // 12.8 KB pooled rows
    __shared__ float red[ROWS_PER_FC][NGRP][NC_];   // 3.75 KB partials

    const int b0 = blockIdx.x * ROWS_PER_FC;
    const int t  = threadIdx.x;

    // ---- Phase A: pooled rows into shared ----
    for (int rc = t; rc < ROWS_PER_FC * J4_; rc += 512) {
        const int r  = rc / J4_;
        const int j4 = rc - r * J4_;
        const int b  = b0 + r;
        const int len = lengths[b];
        float4 s;
        if (len <= 1) {
            s = reinterpret_cast<const float4*>(x + (size_t)b * F_ * JC_)[j4];
        } else {
            const int nch = (len + CHUNK - 1) / CHUNK;
            float ax = 0.f, ay = 0.f, az = 0.f, aw = 0.f;
            for (int c = 0; c < nch; c++) {
                float4 v = g_part[((size_t)b * NCH + c) * J4_ + j4];
                ax += v.x; ay += v.y; az += v.z; aw += v.w;
            }
            const float inv = 1.0f / (float)len;
            s = make_float4(ax * inv, ay * inv, az * inv, aw * inv);
        }
        reinterpret_cast<float4*>(sp[r])[j4] = s;
    }
    __syncthreads();

    // ---- Phase B: coalesced-W dot products ----
    const int n = t & 63;
    const int g = t >> 6;          // 0..7
    if (n < NC_) {
        const int j0 = g * JSEG;
        const float* __restrict__ Wn = W + (size_t)j0 * NC_ + n;
        float acc0 = 0.f, acc1 = 0.f;
#pragma unroll 8
        for (int jj = 0; jj < JSEG; jj++) {
            const float wv = Wn[(size_t)jj * NC_];
            acc0 += sp[0][j0 + jj] * wv;
            acc1 += sp[1][j0 + jj] * wv;
        }
        red[0][g][n] = acc0;
        red[1][g][n] = acc1;
    }
    __syncthreads();

    // ---- Phase C: combine 8 group partials + bias, write out ----
    if (t < ROWS_PER_FC * NC_) {
        const int r = t / NC_;
        const int nn = t - r * NC_;
        float acc = bias[nn];
#pragma unroll
        for (int gg = 0; gg < NGRP; gg++) acc += red[r][gg][nn];
        out[(size_t)(b0 + r) * NC_ + nn] = acc;
    }
}

extern "C" void kernel_launch(void* const* d_in, const int* in_sizes, int n_in,
                              void* d_out, int out_size)
{
    const float* x       = (const float*)d_in[0];
    const int*   lengths = (const int*)  d_in[1];
    const float* W       = (const float*)d_in[2];
    const float* bias    = (const float*)d_in[3];
    float*       out     = (float*)d_out;

    dim3 grid_pool(B_, NCH);
    pool_part_kernel<<<grid_pool, J4_>>>(x, lengths);
    fc_kernel<<<FC_BLOCKS, 512>>>(x, lengths, W, bias, out);
}